// round 8
// baseline (speedup 1.0000x reference)
#include <cuda_runtime.h>

#define BATCH 8
#define CH    64
#define HH    128
#define WW    128
#define NOC   64
#define HW    (HH*WW)

// Weights pre-transformed to [tap][c][oc], each element duplicated into both
// f32x2 lanes of a 64-bit word (so the main loop needs no lane-dup MOVs).
__device__ unsigned long long g_wre[9 * CH * NOC];

__global__ void prep_w(const float* __restrict__ conv) {
    int idx = blockIdx.x * 256 + threadIdx.x;
    if (idx < 9 * CH * NOC) {
        int t  = idx >> 12;          // / 4096
        int r  = idx & 4095;
        int c  = r >> 6;
        int oc = r & 63;
        unsigned int w = __float_as_uint(conv[(oc * CH + c) * 9 + t]);
        g_wre[idx] = ((unsigned long long)w << 32) | (unsigned long long)w;
    }
}

__device__ __forceinline__ void ffma2(unsigned long long& d,
                                      unsigned long long a,
                                      unsigned long long b) {
    asm("fma.rn.f32x2 %0, %1, %2, %0;" : "+l"(d) : "l"(a), "l"(b));
}

__global__ __launch_bounds__(256) void iconv_main(
    const float* __restrict__ inp, const float* __restrict__ mask,
    const float* __restrict__ bias, float* __restrict__ out,
    float* __restrict__ mout)
{
    // k-chunked tiles: 32 channels per phase
    __shared__ __align__(16) float              As[32 * 64];   // [c_local][px]  8 KB
    __shared__ __align__(16) unsigned long long Wd[32 * 64];   // [c_local][oc] 16 KB (dup'd)
    __shared__ float s_meq[9][64];
    __shared__ float s_nrm[64];

    int cta = blockIdx.x;                 // 2048 = 8 b * 128 y * 2 xseg
    int x0  = (cta & 1) << 6;
    int y   = (cta >> 1) & 127;
    int b   = cta >> 8;
    int tid = threadIdx.x;

    // Per-pixel mask-equality bits, renorm factor, and mask_out
    if (tid < 64) {
        int   x  = x0 + tid;
        float m0 = mask[(b * HH + y) * WW + x];
        float cnt = 0.f;
#pragma unroll
        for (int t = 0; t < 9; t++) {
            int dy = t / 3 - 1, dx = t % 3 - 1;
            int yy = y + dy, xx = x + dx;
            float nb = (yy >= 0 && yy < HH && xx >= 0 && xx < WW)
                           ? mask[(b * HH + yy) * WW + xx] : -1.f;
            float e = (nb == m0) ? 1.f : 0.f;
            s_meq[t][tid] = e;
            cnt += e;
        }
        s_nrm[tid] = 9.f / cnt;           // cnt >= 1 (center always matches)
        mout[(b * HH + y) * WW + x] = m0;
    }

    int px0 = (tid & 15) << 2;            // 16 pixel groups * 4 px
    int oc0 = (tid >> 4) << 2;            // 16 oc groups    * 4 oc

    unsigned long long acc[4][2];
#pragma unroll
    for (int j = 0; j < 4; j++) { acc[j][0] = 0ULL; acc[j][1] = 0ULL; }

    for (int t = 0; t < 9; t++) {
        int dy = t / 3 - 1, dx = t % 3 - 1;
        int yy = y + dy;
        const unsigned long long* wsrc = g_wre + t * (CH * NOC);

        for (int h = 0; h < 2; h++) {     // two 32-channel chunks
            __syncthreads();              // prev chunk consumed (1st iter: meq ready)
#pragma unroll
            for (int i = 0; i < 8; i++) { // 2048 elems each tile / 256 threads
                int e = tid + i * 256;
                Wd[e] = wsrc[h * 2048 + e];
                int c  = (e >> 6) + h * 32;
                int px = e & 63;
                int xx = x0 + px + dx;
                float v = 0.f;
                if (yy >= 0 && yy < HH && xx >= 0 && xx < WW)
                    v = inp[((b * CH + c) * HH + yy) * WW + xx] * s_meq[t][px];
                As[e] = v;
            }
            __syncthreads();
#pragma unroll
            for (int k = 0; k < 32; k++) {
                ulonglong2 aP = *(const ulonglong2*)&As[k * 64 + px0]; // 2 px-pairs
                ulonglong2 wA = *(const ulonglong2*)&Wd[k * 64 + oc0];
                ulonglong2 wB = *(const ulonglong2*)&Wd[k * 64 + oc0 + 2];
                ffma2(acc[0][0], wA.x, aP.x); ffma2(acc[0][1], wA.x, aP.y);
                ffma2(acc[1][0], wA.y, aP.x); ffma2(acc[1][1], wA.y, aP.y);
                ffma2(acc[2][0], wB.x, aP.x); ffma2(acc[2][1], wB.x, aP.y);
                ffma2(acc[3][0], wB.y, aP.x); ffma2(acc[3][1], wB.y, aP.y);
            }
        }
    }

    float n0 = s_nrm[px0], n1 = s_nrm[px0 + 1], n2 = s_nrm[px0 + 2], n3 = s_nrm[px0 + 3];
    float4 b4 = *(const float4*)&bias[oc0];
    float bb[4] = {b4.x, b4.y, b4.z, b4.w};
#pragma unroll
    for (int j = 0; j < 4; j++) {
        float4 o;
        o.x = __uint_as_float((unsigned)(acc[j][0]      )) * n0 + bb[j];
        o.y = __uint_as_float((unsigned)(acc[j][0] >> 32)) * n1 + bb[j];
        o.z = __uint_as_float((unsigned)(acc[j][1]      )) * n2 + bb[j];
        o.w = __uint_as_float((unsigned)(acc[j][1] >> 32)) * n3 + bb[j];
        *(float4*)&out[((b * NOC + oc0 + j) * HH + y) * WW + x0 + px0] = o;
    }
}

extern "C" void kernel_launch(void* const* d_in, const int* in_sizes, int n_in,
                              void* d_out, int out_size) {
    const float* inp  = (const float*)d_in[0];   // [8,64,128,128]
    const float* mask = (const float*)d_in[1];   // [8,128,128]
    const float* conv = (const float*)d_in[2];   // [64,64,3,3]
    const float* bias = (const float*)d_in[3];   // [64]
    float* out  = (float*)d_out;                 // [8,64,128,128] then mask_out
    float* mout = out + (size_t)BATCH * NOC * HW;

    prep_w<<<(9 * CH * NOC + 255) / 256, 256>>>(conv);
    iconv_main<<<BATCH * HH * (WW / 64), 256>>>(inp, mask, bias, out, mout);
}

// round 9
// speedup vs baseline: 1.5310x; 1.5310x over previous
#include <cuda_runtime.h>

#define BATCH 8
#define CH    64
#define HHH   128
#define WWW   128
#define NOC   64

typedef unsigned long long u64;

// Weights pre-transformed to [tap][c][oc] plain f32 (coalesced loads, no dup).
__device__ float g_wt[9 * CH * NOC];

__global__ void prep_w(const float* __restrict__ conv) {
    int idx = blockIdx.x * 256 + threadIdx.x;
    if (idx < 9 * CH * NOC) {
        int t = idx >> 12, r = idx & 4095, c = r >> 6, oc = r & 63;
        g_wt[idx] = conv[(oc * CH + c) * 9 + t];
    }
}

__device__ __forceinline__ void ffma2(u64& d, u64 a, u64 b) {
    asm("fma.rn.f32x2 %0, %1, %2, %0;" : "+l"(d) : "l"(a), "l"(b));
}
__device__ __forceinline__ u64 dup2(float x) {
    u64 r; asm("mov.b64 %0, {%1, %1};" : "=l"(r) : "f"(x)); return r;
}
__device__ __forceinline__ float lo32(u64 v) { return __uint_as_float((unsigned)v); }
__device__ __forceinline__ float hi32(u64 v) { return __uint_as_float((unsigned)(v >> 32)); }

__global__ __launch_bounds__(256, 2) void iconv_main(
    const float* __restrict__ inp, const float* __restrict__ mask,
    const float* __restrict__ bias, float* __restrict__ out,
    float* __restrict__ mout)
{
    __shared__ __align__(16) float As[32 * 256];  // [k][px]  32 KB
    __shared__ __align__(16) float Ws[32 * 64];   // [k][oc]   8 KB
    __shared__ unsigned s_mbits[256];
    __shared__ float    s_nrm[256];

    const int cta = blockIdx.x;            // 512 = 8 b * 64 row-pairs
    const int b   = cta >> 6;
    const int y0  = (cta & 63) << 1;       // two image rows per CTA
    const int tid = threadIdx.x;

    // ---- per-pixel mask bits, renorm, mask_out (tid == pixel index) ----
    {
        int row = tid >> 7, x = tid & 127, y = y0 + row;
        float m0 = mask[(b * HHH + y) * WWW + x];
        unsigned bits = 0; float cnt = 0.f;
#pragma unroll
        for (int t = 0; t < 9; t++) {
            int yy = y + t / 3 - 1, xx = x + t % 3 - 1;
            float nb = ((unsigned)yy < 128u && (unsigned)xx < 128u)
                           ? mask[(b * HHH + yy) * WWW + xx] : -1.f;
            if (nb == m0) { bits |= 1u << t; cnt += 1.f; }
        }
        s_mbits[tid] = bits;
        s_nrm[tid]   = 9.f / cnt;          // center always matches -> cnt >= 1
        mout[(b * HHH + y) * WWW + x] = m0;
    }

    const int p0  = (tid & 31) << 2;       // 4 px in row0 (+128 for row1)
    const int oc0 = (tid >> 5) << 3;       // 8 ocs

    u64 acc[8][4];
#pragma unroll
    for (int j = 0; j < 8; j++)
#pragma unroll
        for (int q = 0; q < 4; q++) acc[j][q] = 0ULL;

    for (int t = 0; t < 9; t++) {
        const int dy = t / 3 - 1, dx = t % 3 - 1;
        for (int h = 0; h < 2; h++) {      // two 32-channel k-chunks
            __syncthreads();               // tiles consumed (1st iter: mbits ready)

            // ---- build A: this thread's pixel, all 32 channels ----
            {
                int row = tid >> 7, xx = (tid & 127) + dx, yy = y0 + row + dy;
                bool inb = ((unsigned)yy < 128u) && ((unsigned)xx < 128u);
                float gate = (inb && ((s_mbits[tid] >> t) & 1)) ? 1.f : 0.f;
                const float* ip = inp + (((size_t)b * CH + h * 32) * HHH
                                         + (inb ? yy : 0)) * WWW + (inb ? xx : 0);
#pragma unroll
                for (int kl = 0; kl < 32; kl++)
                    As[kl * 256 + tid] = ip[kl * (HHH * WWW)] * gate;
            }
            // ---- build W chunk ----
            {
                const float* wsrc = g_wt + t * (CH * NOC) + h * 2048;
#pragma unroll
                for (int i = 0; i < 8; i++)
                    Ws[tid + i * 256] = wsrc[tid + i * 256];
            }
            __syncthreads();

            // ---- 64 FMAs per thread per k ----
#pragma unroll 8
            for (int k = 0; k < 32; k++) {
                ulonglong2 aA = *(const ulonglong2*)&As[k * 256 + p0];        // px p0..p0+3
                ulonglong2 aB = *(const ulonglong2*)&As[k * 256 + p0 + 128];  // row1
                float4 w0 = *(const float4*)&Ws[k * 64 + oc0];                // broadcast
                float4 w1 = *(const float4*)&Ws[k * 64 + oc0 + 4];
                u64 wd[8] = { dup2(w0.x), dup2(w0.y), dup2(w0.z), dup2(w0.w),
                              dup2(w1.x), dup2(w1.y), dup2(w1.z), dup2(w1.w) };
#pragma unroll
                for (int j = 0; j < 8; j++) {
                    ffma2(acc[j][0], wd[j], aA.x);
                    ffma2(acc[j][1], wd[j], aA.y);
                    ffma2(acc[j][2], wd[j], aB.x);
                    ffma2(acc[j][3], wd[j], aB.y);
                }
            }
        }
    }

    // ---- epilogue: renorm + bias, vectorized stores ----
    float nr[8];
#pragma unroll
    for (int q = 0; q < 4; q++) {
        nr[q]     = s_nrm[p0 + q];
        nr[4 + q] = s_nrm[128 + p0 + q];
    }
#pragma unroll
    for (int j = 0; j < 8; j++) {
        float bb = bias[oc0 + j];
        float4 o0, o1;
        o0.x = lo32(acc[j][0]) * nr[0] + bb;  o0.y = hi32(acc[j][0]) * nr[1] + bb;
        o0.z = lo32(acc[j][1]) * nr[2] + bb;  o0.w = hi32(acc[j][1]) * nr[3] + bb;
        o1.x = lo32(acc[j][2]) * nr[4] + bb;  o1.y = hi32(acc[j][2]) * nr[5] + bb;
        o1.z = lo32(acc[j][3]) * nr[6] + bb;  o1.w = hi32(acc[j][3]) * nr[7] + bb;
        size_t base = (((size_t)b * NOC + oc0 + j) * HHH + y0) * WWW;
        *(float4*)&out[base + p0]       = o0;
        *(float4*)&out[base + WWW + p0] = o1;
    }
}

extern "C" void kernel_launch(void* const* d_in, const int* in_sizes, int n_in,
                              void* d_out, int out_size) {
    const float* inp  = (const float*)d_in[0];   // [8,64,128,128]
    const float* mask = (const float*)d_in[1];   // [8,128,128]
    const float* conv = (const float*)d_in[2];   // [64,64,3,3]
    const float* bias = (const float*)d_in[3];   // [64]
    float* out  = (float*)d_out;                 // [8,64,128,128] then mask_out
    float* mout = out + (size_t)BATCH * NOC * HHH * WWW;

    prep_w<<<(9 * CH * NOC + 255) / 256, 256>>>(conv);
    iconv_main<<<BATCH * (HHH / 2), 256>>>(inp, mask, bias, out, mout);
}

// round 12
// speedup vs baseline: 3.6216x; 2.3656x over previous
#include <cuda_runtime.h>
#include <cstdint>

#define BATCH 8

// Pre-rounded tf32 weights, padded image: [s=tap*2+half][oc*36 + ch] (36-stride pad)
__device__ float g_wb[18 * 2304];

__global__ void prep_w(const float* __restrict__ conv) {
    int idx = blockIdx.x * 256 + threadIdx.x;       // 18*2048 real elements
    if (idx < 18 * 2048) {
        int s = idx >> 11, r = idx & 2047;
        int oc = r >> 5, ch = r & 31;
        int t = s >> 1, h = s & 1;
        float w = conv[(oc * 64 + h * 32 + ch) * 9 + t];
        uint32_t v; asm("cvt.rna.tf32.f32 %0, %1;" : "=r"(v) : "f"(w));
        g_wb[s * 2304 + oc * 36 + ch] = __uint_as_float(v);
    }
}

static __device__ __forceinline__ void mma_tf32(float* d, const uint32_t* a,
                                                const uint32_t* b) {
    asm volatile(
        "mma.sync.aligned.m16n8k8.row.col.f32.tf32.tf32.f32 "
        "{%0,%1,%2,%3}, {%4,%5,%6,%7}, {%8,%9}, {%0,%1,%2,%3};"
        : "+f"(d[0]), "+f"(d[1]), "+f"(d[2]), "+f"(d[3])
        : "r"(a[0]), "r"(a[1]), "r"(a[2]), "r"(a[3]), "r"(b[0]), "r"(b[1]));
}

__global__ __launch_bounds__(128, 4) void iconv_mma(
    const float* __restrict__ inp, const float* __restrict__ mask,
    const float* __restrict__ bias, float* __restrict__ out,
    float* __restrict__ mout)
{
    __shared__ float As[32 * 132];   // [ch][px] stride-132 pad : 16.9 KB
    __shared__ float Bs[2304];       // [oc][ch] stride-36 pad  :  9.2 KB
    __shared__ float s_nrm[128];
    __shared__ float s_bias[64];

    const int tid  = threadIdx.x;
    const int lane = tid & 31;
    const int wp   = tid >> 5;
    const int b    = blockIdx.x >> 7;
    const int y    = blockIdx.x & 127;

    // ---- per-pixel (px = tid) mask bits, renorm, mask_out ----
    float m0 = mask[(b * 128 + y) * 128 + tid];
    unsigned mbits = 0; float cnt = 0.f;
#pragma unroll
    for (int t = 0; t < 9; t++) {
        int yy = y + t / 3 - 1, xx = tid + t % 3 - 1;
        float nb = ((unsigned)yy < 128u && (unsigned)xx < 128u)
                       ? mask[(b * 128 + yy) * 128 + xx] : -1.f;
        if (nb == m0) { mbits |= 1u << t; cnt += 1.f; }
    }
    s_nrm[tid] = 9.f / cnt;                         // center always matches
    mout[(b * 128 + y) * 128 + tid] = m0;
    if (tid < 64) s_bias[tid] = bias[tid];

    float acc[2][8][4];
#pragma unroll
    for (int mi = 0; mi < 2; mi++)
#pragma unroll
        for (int ni = 0; ni < 8; ni++)
#pragma unroll
            for (int r = 0; r < 4; r++) acc[mi][ni][r] = 0.f;

    // ---- 18 K-chunks: tap t, channel-half h ----
    for (int s = 0; s < 18; s++) {
        const int t = s >> 1, h = s & 1;
        const int dy = t / 3 - 1, dx = t % 3 - 1;
        __syncthreads();                            // previous tiles consumed

        // B chunk: linear copy of pre-padded image (coalesced, conflict-free)
        {
            const float* wsrc = g_wb + s * 2304;
#pragma unroll
            for (int i = 0; i < 18; i++) Bs[tid + i * 128] = wsrc[tid + i * 128];
        }
        // A chunk: this thread's pixel, 32 gated tf32 channels
        {
            int yy = y + dy, xx = tid + dx;
            bool inb = ((unsigned)yy < 128u) && ((unsigned)xx < 128u);
            float gate = (inb && ((mbits >> t) & 1)) ? 1.f : 0.f;
            const float* ip = inp + (((size_t)b * 64 + h * 32) * 128 + (inb ? yy : 0)) * 128
                                  + (inb ? xx : 0);
#pragma unroll
            for (int c = 0; c < 32; c++) {
                float v = ip[(size_t)c * 16384] * gate;
                uint32_t tv; asm("cvt.rna.tf32.f32 %0, %1;" : "=r"(tv) : "f"(v));
                As[c * 132 + tid] = __uint_as_float(tv);
            }
        }
        __syncthreads();

        // mma phase: warp tile 32 px x 64 oc
        const int px0 = wp * 32;
#pragma unroll
        for (int k0 = 0; k0 < 32; k0 += 8) {
            uint32_t a[2][4], bf[8][2];
            const int c0 = k0 + (lane & 3);
            const int rr = lane >> 2;
#pragma unroll
            for (int mi = 0; mi < 2; mi++) {
                int pxb = px0 + mi * 16 + rr;
                a[mi][0] = __float_as_uint(As[c0 * 132 + pxb]);
                a[mi][1] = __float_as_uint(As[c0 * 132 + pxb + 8]);
                a[mi][2] = __float_as_uint(As[(c0 + 4) * 132 + pxb]);
                a[mi][3] = __float_as_uint(As[(c0 + 4) * 132 + pxb + 8]);
            }
#pragma unroll
            for (int ni = 0; ni < 8; ni++) {
                int ocb = ni * 8 + rr;
                bf[ni][0] = __float_as_uint(Bs[ocb * 36 + c0]);
                bf[ni][1] = __float_as_uint(Bs[ocb * 36 + c0 + 4]);
            }
#pragma unroll
            for (int mi = 0; mi < 2; mi++)
#pragma unroll
                for (int ni = 0; ni < 8; ni++)
                    mma_tf32(acc[mi][ni], a[mi], bf[ni]);
        }
    }

    // ---- epilogue: stage 16-oc slabs through smem -> coalesced stores ----
#pragma unroll
    for (int og = 0; og < 4; og++) {
        __syncthreads();
#pragma unroll
        for (int mi = 0; mi < 2; mi++)
#pragma unroll
            for (int nj = 0; nj < 2; nj++) {
                int ni = og * 2 + nj;
#pragma unroll
                for (int r = 0; r < 4; r++) {
                    int px  = wp * 32 + mi * 16 + (lane >> 2) + ((r & 2) ? 8 : 0);
                    int ocl = nj * 8 + 2 * (lane & 3) + (r & 1);
                    As[ocl * 132 + px] = acc[mi][ni][r];
                }
            }
        __syncthreads();
#pragma unroll
        for (int ocl = 0; ocl < 16; ocl++) {
            int oc = og * 16 + ocl;
            out[(((size_t)b * 64 + oc) * 128 + y) * 128 + tid] =
                As[ocl * 132 + tid] * s_nrm[tid] + s_bias[oc];
        }
    }
}

extern "C" void kernel_launch(void* const* d_in, const int* in_sizes, int n_in,
                              void* d_out, int out_size) {
    const float* inp  = (const float*)d_in[0];   // [8,64,128,128]
    const float* mask = (const float*)d_in[1];   // [8,128,128]
    const float* conv = (const float*)d_in[2];   // [64,64,3,3]
    const float* bias = (const float*)d_in[3];   // [64]
    float* out  = (float*)d_out;                 // [8,64,128,128] then mask_out
    float* mout = out + (size_t)BATCH * 64 * 128 * 128;

    prep_w<<<144, 256>>>(conv);
    iconv_mma<<<BATCH * 128, 128>>>(inp, mask, bias, out, mout);
}

// round 13
// speedup vs baseline: 3.8740x; 1.0697x over previous
#include <cuda_runtime.h>
#include <cstdint>

#define BATCH 8

// B in mma-fragment order: [s(18)][kstep(4)][ni(8)][lane(32)] -> float2 {w(k), w(k+4)}
__device__ float2 g_bf[18 * 4 * 8 * 32];

__global__ void prep_w(const float* __restrict__ conv) {
    int idx = blockIdx.x * 256 + threadIdx.x;          // 18432 fragments
    if (idx < 18432) {
        int lane = idx & 31;
        int ni   = (idx >> 5) & 7;
        int kk   = (idx >> 8) & 3;
        int s    = idx >> 10;
        int t = s >> 1, h = s & 1;
        int oc  = ni * 8 + (lane >> 2);
        int ch0 = h * 32 + kk * 8 + (lane & 3);
        float w0 = conv[(oc * 64 + ch0) * 9 + t];
        float w1 = conv[(oc * 64 + ch0 + 4) * 9 + t];
        uint32_t v0, v1;
        asm("cvt.rna.tf32.f32 %0, %1;" : "=r"(v0) : "f"(w0));
        asm("cvt.rna.tf32.f32 %0, %1;" : "=r"(v1) : "f"(w1));
        g_bf[idx] = make_float2(__uint_as_float(v0), __uint_as_float(v1));
    }
}

static __device__ __forceinline__ void mma_tf32(float* d, const uint32_t* a,
                                                uint32_t b0, uint32_t b1) {
    asm volatile(
        "mma.sync.aligned.m16n8k8.row.col.f32.tf32.tf32.f32 "
        "{%0,%1,%2,%3}, {%4,%5,%6,%7}, {%8,%9}, {%0,%1,%2,%3};"
        : "+f"(d[0]), "+f"(d[1]), "+f"(d[2]), "+f"(d[3])
        : "r"(a[0]), "r"(a[1]), "r"(a[2]), "r"(a[3]), "r"(b0), "r"(b1));
}

__global__ __launch_bounds__(128, 3) void iconv_mma(
    const float* __restrict__ inp, const float* __restrict__ mask,
    const float* __restrict__ bias, float* __restrict__ out,
    float* __restrict__ mout)
{
    __shared__ float As[2 * 32 * 132];   // double-buffered [ch][px] pad-132 : 33 KB
    __shared__ float s_nrm[128];
    __shared__ float s_bias[64];

    const int tid  = threadIdx.x;
    const int lane = tid & 31;
    const int wp   = tid >> 5;
    const int b    = blockIdx.x >> 7;
    const int y    = blockIdx.x & 127;

    // ---- per-pixel (px = tid) mask bits, renorm, mask_out ----
    float m0 = mask[(b * 128 + y) * 128 + tid];
    unsigned mbits = 0; float cnt = 0.f;
#pragma unroll
    for (int t = 0; t < 9; t++) {
        int yy = y + t / 3 - 1, xx = tid + t % 3 - 1;
        float nb = ((unsigned)yy < 128u && (unsigned)xx < 128u)
                       ? mask[(b * 128 + yy) * 128 + xx] : -1.f;
        if (nb == m0) { mbits |= 1u << t; cnt += 1.f; }
    }
    s_nrm[tid] = 9.f / cnt;                             // center always matches
    mout[(b * 128 + y) * 128 + tid] = m0;
    if (tid < 64) s_bias[tid] = bias[tid];

    float acc[2][8][4];
#pragma unroll
    for (int mi = 0; mi < 2; mi++)
#pragma unroll
        for (int ni = 0; ni < 8; ni++)
#pragma unroll
            for (int r = 0; r < 4; r++) acc[mi][ni][r] = 0.f;

    // ---- prologue: build chunk 0 into buffer 0 ----
    {
        int yy = y - 1, xx = tid - 1;                   // t=0 -> dy=-1, dx=-1
        bool inb = ((unsigned)yy < 128u) && ((unsigned)xx < 128u);
        float gate = (inb && (mbits & 1u)) ? 1.f : 0.f;
        const float* ip = inp + ((size_t)b * 64 * 128 + (inb ? yy : 0)) * 128
                              + (inb ? xx : 0);
#pragma unroll
        for (int c = 0; c < 32; c++) {
            uint32_t tv;
            float v = ip[(size_t)c * 16384] * gate;
            asm("cvt.rna.tf32.f32 %0, %1;" : "=r"(tv) : "f"(v));
            As[c * 132 + tid] = __uint_as_float(tv);
        }
    }
    __syncthreads();

    // ---- 18 chunks, software-pipelined ----
    const int px0 = wp * 32;
    for (int s = 0; s < 18; s++) {
        const int p = s & 1;

        // prefetch chunk s+1 A into registers (LDGs issue before MMAs)
        float va[32]; float gate = 0.f;
        const bool have_next = (s + 1 < 18);
        if (have_next) {
            int t = (s + 1) >> 1, h = (s + 1) & 1;
            int yy = y + t / 3 - 1, xx = tid + t % 3 - 1;
            bool inb = ((unsigned)yy < 128u) && ((unsigned)xx < 128u);
            gate = (inb && ((mbits >> t) & 1)) ? 1.f : 0.f;
            const float* ip = inp + (((size_t)b * 64 + h * 32) * 128 + (inb ? yy : 0)) * 128
                                  + (inb ? xx : 0);
#pragma unroll
            for (int c = 0; c < 32; c++) va[c] = ip[(size_t)c * 16384];
        }

        // MMA phase on buffer p; B frags straight from L1/L2-resident global
        {
            const float* A = As + p * 4224;
#pragma unroll
            for (int kk = 0; kk < 4; kk++) {
                const int c0 = kk * 8 + (lane & 3);
                const int rr = lane >> 2;
                uint32_t a[2][4];
#pragma unroll
                for (int mi = 0; mi < 2; mi++) {
                    int pxb = px0 + mi * 16 + rr;
                    a[mi][0] = __float_as_uint(A[c0 * 132 + pxb]);
                    a[mi][1] = __float_as_uint(A[c0 * 132 + pxb + 8]);
                    a[mi][2] = __float_as_uint(A[(c0 + 4) * 132 + pxb]);
                    a[mi][3] = __float_as_uint(A[(c0 + 4) * 132 + pxb + 8]);
                }
                const float2* bf = g_bf + ((s * 4 + kk) * 8) * 32 + lane;
#pragma unroll
                for (int ni = 0; ni < 8; ni++) {
                    float2 bv = bf[ni * 32];
                    uint32_t b0 = __float_as_uint(bv.x), b1 = __float_as_uint(bv.y);
                    mma_tf32(acc[0][ni], a[0], b0, b1);
                    mma_tf32(acc[1][ni], a[1], b0, b1);
                }
            }
        }

        // store prefetched chunk into the other buffer
        if (have_next) {
            float* D = As + (p ^ 1) * 4224;
#pragma unroll
            for (int c = 0; c < 32; c++) {
                uint32_t tv;
                float v = va[c] * gate;
                asm("cvt.rna.tf32.f32 %0, %1;" : "=r"(tv) : "f"(v));
                D[c * 132 + tid] = __uint_as_float(tv);
            }
        }
        __syncthreads();
    }

    // ---- epilogue: stage 16-oc slabs through smem -> coalesced stores ----
#pragma unroll
    for (int og = 0; og < 4; og++) {
        __syncthreads();
#pragma unroll
        for (int mi = 0; mi < 2; mi++)
#pragma unroll
            for (int nj = 0; nj < 2; nj++) {
                int ni = og * 2 + nj;
#pragma unroll
                for (int r = 0; r < 4; r++) {
                    int px  = wp * 32 + mi * 16 + (lane >> 2) + ((r & 2) ? 8 : 0);
                    int ocl = nj * 8 + 2 * (lane & 3) + (r & 1);
                    As[ocl * 132 + px] = acc[mi][ni][r];
                }
            }
        __syncthreads();
#pragma unroll
        for (int ocl = 0; ocl < 16; ocl++) {
            int oc = og * 16 + ocl;
            out[(((size_t)b * 64 + oc) * 128 + y) * 128 + tid] =
                As[ocl * 132 + tid] * s_nrm[tid] + s_bias[oc];
        }
    }
}

extern "C" void kernel_launch(void* const* d_in, const int* in_sizes, int n_in,
                              void* d_out, int out_size) {
    const float* inp  = (const float*)d_in[0];   // [8,64,128,128]
    const float* mask = (const float*)d_in[1];   // [8,128,128]
    const float* conv = (const float*)d_in[2];   // [64,64,3,3]
    const float* bias = (const float*)d_in[3];   // [64]
    float* out  = (float*)d_out;                 // [8,64,128,128] then mask_out
    float* mout = out + (size_t)BATCH * 64 * 128 * 128;

    prep_w<<<72, 256>>>(conv);
    iconv_mma<<<BATCH * 128, 128>>>(inp, mask, bias, out, mout);
}

// round 15
// speedup vs baseline: 5.0575x; 1.3055x over previous
#include <cuda_runtime.h>
#include <cstdint>

#define BATCH 8

// B in mma-fragment order: [t(9)][kk(8)][ni(8)][lane(32)] -> float2 {w(k), w(k+4)}
__device__ float2 g_bf[9 * 8 * 8 * 32];

__global__ void prep_w(const float* __restrict__ conv) {
    int idx = blockIdx.x * 256 + threadIdx.x;          // 18432 fragments
    if (idx < 18432) {
        int lane = idx & 31;
        int ni   = (idx >> 5) & 7;
        int kk   = (idx >> 8) & 7;
        int t    = idx >> 11;
        int oc  = ni * 8 + (lane >> 2);
        int ch0 = kk * 8 + (lane & 3);
        float w0 = conv[(oc * 64 + ch0) * 9 + t];
        float w1 = conv[(oc * 64 + ch0 + 4) * 9 + t];
        uint32_t v0, v1;
        asm("cvt.rna.tf32.f32 %0, %1;" : "=r"(v0) : "f"(w0));
        asm("cvt.rna.tf32.f32 %0, %1;" : "=r"(v1) : "f"(w1));
        g_bf[idx] = make_float2(__uint_as_float(v0), __uint_as_float(v1));
    }
}

static __device__ __forceinline__ void mma_tf32(float* d, const uint32_t* a,
                                                uint32_t b0, uint32_t b1) {
    asm volatile(
        "mma.sync.aligned.m16n8k8.row.col.f32.tf32.tf32.f32 "
        "{%0,%1,%2,%3}, {%4,%5,%6,%7}, {%8,%9}, {%0,%1,%2,%3};"
        : "+f"(d[0]), "+f"(d[1]), "+f"(d[2]), "+f"(d[3])
        : "r"(a[0]), "r"(a[1]), "r"(a[2]), "r"(a[3]), "r"(b0), "r"(b1));
}

__global__ __launch_bounds__(128, 4) void iconv_mma(
    const float* __restrict__ inp, const float* __restrict__ mask,
    const float* __restrict__ bias, float* __restrict__ out,
    float* __restrict__ mout)
{
    __shared__ float As[64 * 132];       // one raw input row: [ch][pxcol] 33 KB
    __shared__ unsigned s_mbits[128];
    __shared__ float s_nrm[128];
    __shared__ float s_bias[64];

    const int tid  = threadIdx.x;
    const int lane = tid & 31;
    const int wp   = tid >> 5;
    const int b    = blockIdx.x >> 7;
    const int y    = blockIdx.x & 127;

    // ---- per-pixel (px = tid) mask bits, renorm, mask_out ----
    float m0 = mask[(b * 128 + y) * 128 + tid];
    unsigned mbits = 0; float cnt = 0.f;
#pragma unroll
    for (int t = 0; t < 9; t++) {
        int yy = y + t / 3 - 1, xx = tid + t % 3 - 1;
        float nb = ((unsigned)yy < 128u && (unsigned)xx < 128u)
                       ? mask[(b * 128 + yy) * 128 + xx] : -1.f;
        if (nb == m0) { mbits |= 1u << t; cnt += 1.f; }
    }
    s_mbits[tid] = mbits;
    s_nrm[tid]   = 9.f / cnt;                           // center always matches
    mout[(b * 128 + y) * 128 + tid] = m0;
    if (tid < 64) s_bias[tid] = bias[tid];

    // halo columns 0 and 129 are permanently zero (xx = -1 / 128)
    if (tid < 64)       As[tid * 132]               = 0.f;
    else                As[(tid - 64) * 132 + 129]  = 0.f;

    float acc[2][8][4];
#pragma unroll
    for (int mi = 0; mi < 2; mi++)
#pragma unroll
        for (int ni = 0; ni < 8; ni++)
#pragma unroll
            for (int r = 0; r < 4; r++) acc[mi][ni][r] = 0.f;

    const int px0 = wp * 32;
    const int rr  = lane >> 2;
    const int cc  = lane & 3;

    for (int dy = -1; dy <= 1; dy++) {
        const int yy = y + dy;
        if ((unsigned)yy >= 128u) continue;             // gates are 0 for these taps

        __syncthreads();                                // prior tap-group done with As
        {   // load raw row y+dy: this thread's px, all 64 channels (tf32-rounded)
            const float* ip = inp + ((size_t)b * 64 * 128 + yy) * 128 + tid;
#pragma unroll
            for (int c = 0; c < 64; c++) {
                uint32_t tv;
                float v = ip[(size_t)c * 16384];
                asm("cvt.rna.tf32.f32 %0, %1;" : "=r"(tv) : "f"(v));
                As[c * 132 + tid + 1] = __uint_as_float(tv);
            }
        }
        __syncthreads();

#pragma unroll
        for (int dx = -1; dx <= 1; dx++) {
            const int t = (dy + 1) * 3 + (dx + 1);
            // per-thread gates for its 4 fragment rows
            float g[2][2];
#pragma unroll
            for (int mi = 0; mi < 2; mi++) {
                g[mi][0] = ((s_mbits[px0 + mi * 16 + rr]     >> t) & 1) ? 1.f : 0.f;
                g[mi][1] = ((s_mbits[px0 + mi * 16 + rr + 8] >> t) & 1) ? 1.f : 0.f;
            }
#pragma unroll
            for (int kk = 0; kk < 8; kk++) {
                const int c0 = kk * 8 + cc;
                uint32_t a[2][4];
#pragma unroll
                for (int mi = 0; mi < 2; mi++) {
                    int col = px0 + mi * 16 + rr + dx + 1;
                    float a0 = As[c0 * 132 + col]       * g[mi][0];
                    float a1 = As[c0 * 132 + col + 8]   * g[mi][1];
                    float a2 = As[(c0 + 4) * 132 + col]     * g[mi][0];
                    float a3 = As[(c0 + 4) * 132 + col + 8] * g[mi][1];
                    a[mi][0] = __float_as_uint(a0); a[mi][1] = __float_as_uint(a1);
                    a[mi][2] = __float_as_uint(a2); a[mi][3] = __float_as_uint(a3);
                }
                const float2* bf = g_bf + ((t * 8 + kk) * 8) * 32 + lane;
#pragma unroll
                for (int ni = 0; ni < 8; ni++) {
                    float2 bv = bf[ni * 32];
                    uint32_t b0 = __float_as_uint(bv.x), b1 = __float_as_uint(bv.y);
                    mma_tf32(acc[0][ni], a[0], b0, b1);
                    mma_tf32(acc[1][ni], a[1], b0, b1);
                }
            }
        }
    }

    // ---- epilogue: stage 16-oc slabs through smem -> coalesced stores ----
#pragma unroll
    for (int og = 0; og < 4; og++) {
        __syncthreads();
#pragma unroll
        for (int mi = 0; mi < 2; mi++)
#pragma unroll
            for (int nj = 0; nj < 2; nj++) {
                int ni = og * 2 + nj;
#pragma unroll
                for (int r = 0; r < 4; r++) {
                    int px  = px0 + mi * 16 + rr + ((r & 2) ? 8 : 0);
                    int ocl = nj * 8 + 2 * cc + (r & 1);
                    As[ocl * 132 + px] = acc[mi][ni][r];
                }
            }
        __syncthreads();
#pragma unroll
        for (int ocl = 0; ocl < 16; ocl++) {
            int oc = og * 16 + ocl;
            out[(((size_t)b * 64 + oc) * 128 + y) * 128 + tid] =
                As[ocl * 132 + tid] * s_nrm[tid] + s_bias[oc];
        }
    }
}

extern "C" void kernel_launch(void* const* d_in, const int* in_sizes, int n_in,
                              void* d_out, int out_size) {
    const float* inp  = (const float*)d_in[0];   // [8,64,128,128]
    const float* mask = (const float*)d_in[1];   // [8,128,128]
    const float* conv = (const float*)d_in[2];   // [64,64,3,3]
    const float* bias = (const float*)d_in[3];   // [64]
    float* out  = (float*)d_out;                 // [8,64,128,128] then mask_out
    float* mout = out + (size_t)BATCH * 64 * 128 * 128;

    prep_w<<<72, 256>>>(conv);
    iconv_mma<<<BATCH * 128, 128>>>(inp, mask, bias, out, mout);
}